// round 3
// baseline (speedup 1.0000x reference)
#include <cuda_runtime.h>

// Sparsemax over rows of a 16384 x 4096 fp32 matrix.
// Persistent CTAs, grid-stride over rows, software-pipelined:
// next row's loads are issued BEFORE the current row's tau computation,
// so the barrier/Michelot phase overlaps with memory traffic.
//
// tau* >= rowmax - 1, so only elements > rowmax - 1 can be in the support
// (~5-30 per row for Gaussian data). Michelot's fixed-point iteration on
// that candidate superset converges exactly in a few steps.

#define N_COLS   4096
#define THREADS  256
#define CAND_CAP 4096   // == N_COLS: overflow structurally impossible
#define NBLOCKS  456    // 152 SMs * 3 CTAs -> one persistent wave

__global__ __launch_bounds__(THREADS, 3)
void sparsemax_kernel(const float* __restrict__ x, float* __restrict__ out,
                      int rows) {
    const int tid  = threadIdx.x;
    const int lane = tid & 31;
    const int wid  = tid >> 5;

    __shared__ float warp_max[THREADS / 32];
    __shared__ float sh_max;
    __shared__ float sh_tau;
    __shared__ int   sh_cnt;
    __shared__ float cand[CAND_CAP];

    if (tid == 0) sh_cnt = 0;   // visible before first gather (2 barriers away)

    const int stride = gridDim.x;
    int r = blockIdx.x;

    // ---- prologue: load first row ----
    float4 v[4];
    if (r < rows) {
        const float4* xr = reinterpret_cast<const float4*>(x + (size_t)r * N_COLS);
#pragma unroll
        for (int k = 0; k < 4; k++) v[k] = __ldcs(&xr[tid + k * THREADS]);
    }

    for (; r < rows; r += stride) {
        // ---- issue next row's loads NOW (overlap with tau phase) ----
        const int rn = r + stride;
        float4 vn[4];
        if (rn < rows) {
            const float4* xrn = reinterpret_cast<const float4*>(x + (size_t)rn * N_COLS);
#pragma unroll
            for (int k = 0; k < 4; k++) vn[k] = __ldcs(&xrn[tid + k * THREADS]);
        }

        // ---- row max: warp shfl reduce + cross-warp via shared ----
        float m = fmaxf(fmaxf(v[0].x, v[0].y), fmaxf(v[0].z, v[0].w));
#pragma unroll
        for (int k = 1; k < 4; k++)
            m = fmaxf(m, fmaxf(fmaxf(v[k].x, v[k].y), fmaxf(v[k].z, v[k].w)));
#pragma unroll
        for (int o = 16; o > 0; o >>= 1)
            m = fmaxf(m, __shfl_xor_sync(0xffffffffu, m, o));
        if (lane == 0) warp_max[wid] = m;
        __syncthreads();
        if (tid == 0) {
            float mm = warp_max[0];
#pragma unroll
            for (int i = 1; i < THREADS / 32; i++) mm = fmaxf(mm, warp_max[i]);
            sh_max = mm;
        }
        __syncthreads();

        const float thresh = sh_max - 1.0f;   // tau* >= thresh always

        // ---- gather candidates (x > rowmax - 1) into shared ----
#pragma unroll
        for (int k = 0; k < 4; k++) {
            float vals[4] = {v[k].x, v[k].y, v[k].z, v[k].w};
#pragma unroll
            for (int j = 0; j < 4; j++) {
                if (vals[j] > thresh) {
                    int p = atomicAdd(&sh_cnt, 1);
                    cand[p] = vals[j];
                }
            }
        }
        __syncthreads();

        // ---- warp 0: Michelot fixed-point on the tiny candidate set ----
        if (wid == 0) {
            const int n = sh_cnt;     // >= 1 (rowmax itself)
            float t = thresh;
            int c_prev = -1;
            for (int iter = 0; iter <= CAND_CAP; iter++) {
                float s = 0.0f;
                int   c = 0;
                for (int i = lane; i < n; i += 32) {
                    float z = cand[i];
                    if (z > t) { s += z; c++; }
                }
#pragma unroll
                for (int o = 16; o > 0; o >>= 1) {
                    s += __shfl_xor_sync(0xffffffffu, s, o);
                    c += __shfl_xor_sync(0xffffffffu, c, o);
                }
                if (c == c_prev) break;       // support stabilized -> exact tau
                t = (s - 1.0f) / (float)c;    // c >= 1 always
                c_prev = c;
            }
            if (lane == 0) { sh_tau = t; sh_cnt = 0; }  // reset for next row
        }
        __syncthreads();
        const float tau = sh_tau;

        // ---- write max(x - tau, 0), streaming stores ----
        float4* orow = reinterpret_cast<float4*>(out + (size_t)r * N_COLS);
#pragma unroll
        for (int k = 0; k < 4; k++) {
            float4 o;
            o.x = fmaxf(v[k].x - tau, 0.0f);
            o.y = fmaxf(v[k].y - tau, 0.0f);
            o.z = fmaxf(v[k].z - tau, 0.0f);
            o.w = fmaxf(v[k].w - tau, 0.0f);
            __stcs(&orow[tid + k * THREADS], o);
        }

        // ---- rotate pipeline ----
#pragma unroll
        for (int k = 0; k < 4; k++) v[k] = vn[k];
    }
}

extern "C" void kernel_launch(void* const* d_in, const int* in_sizes, int n_in,
                              void* d_out, int out_size) {
    const float* x = (const float*)d_in[0];
    float* out = (float*)d_out;
    const int rows = in_sizes[0] / N_COLS;   // 16384
    sparsemax_kernel<<<NBLOCKS, THREADS>>>(x, out, rows);
}

// round 4
// speedup vs baseline: 1.2357x; 1.2357x over previous
#include <cuda_runtime.h>
#include <cstdint>

// Sparsemax over rows of 16384 x 4096 fp32.
// Persistent CTAs; next row prefetched via cp.async (LDGSTS) into a shared
// double buffer -> zero register cost for pipelining, 6 CTAs/SM.
// Sort-free exact tau: candidates {x > rowmax-1} + Michelot fixed point
// (exact, monotone support shrinkage). Full-row fallback if candidate
// buffer overflows (structurally correct for any input).

#define N_COLS      4096
#define THREADS     256
#define CAND_CAP    1024
#define CTAS_PER_SM 6
#define NBLOCKS     (152 * CTAS_PER_SM)   // one persistent wave on GB300

__device__ __forceinline__ unsigned enc_f(float f) {
    unsigned u = __float_as_uint(f);
    return (u & 0x80000000u) ? ~u : (u | 0x80000000u);   // order-preserving
}
__device__ __forceinline__ float dec_f(unsigned e) {
    unsigned u = (e & 0x80000000u) ? (e & 0x7fffffffu) : ~e;
    return __uint_as_float(u);
}

__global__ __launch_bounds__(THREADS, CTAS_PER_SM)
void sparsemax_kernel(const float* __restrict__ x, float* __restrict__ out,
                      int rows) {
    __shared__ float    buf[2][N_COLS];     // 32 KB double buffer
    __shared__ float    cand[CAND_CAP];     // 4 KB
    __shared__ unsigned sh_maxbits;
    __shared__ float    sh_tau;
    __shared__ int      sh_cnt;

    const int tid    = threadIdx.x;
    const int lane   = tid & 31;
    const int wid    = tid >> 5;
    const int stride = gridDim.x;

    // ---- prologue: prefetch first row ----
    int r0 = blockIdx.x;
    if (r0 < rows) {
        const float4* g = reinterpret_cast<const float4*>(x + (size_t)r0 * N_COLS);
        uint32_t s = (uint32_t)__cvta_generic_to_shared(&buf[0][0]);
#pragma unroll
        for (int k = 0; k < 4; k++) {
            uint32_t saddr = s + (uint32_t)(tid + k * THREADS) * 16u;
            asm volatile("cp.async.cg.shared.global [%0], [%1], 16;\n"
                         :: "r"(saddr), "l"(g + tid + k * THREADS));
        }
    }
    asm volatile("cp.async.commit_group;\n" ::: "memory");

    int p = 0;
    for (int r = r0; r < rows; r += stride, p ^= 1) {
        // ---- prefetch next row into buf[p^1] (overlaps this row's tau) ----
        const int rn = r + stride;
        if (rn < rows) {
            const float4* g = reinterpret_cast<const float4*>(x + (size_t)rn * N_COLS);
            uint32_t s = (uint32_t)__cvta_generic_to_shared(&buf[p ^ 1][0]);
#pragma unroll
            for (int k = 0; k < 4; k++) {
                uint32_t saddr = s + (uint32_t)(tid + k * THREADS) * 16u;
                asm volatile("cp.async.cg.shared.global [%0], [%1], 16;\n"
                             :: "r"(saddr), "l"(g + tid + k * THREADS));
            }
        }
        asm volatile("cp.async.commit_group;\n" ::: "memory");

        if (tid == 0) { sh_maxbits = 0u; sh_cnt = 0; }   // ordered by barrier below

        // wait for buf[p] (the older group), leave the prefetch in flight
        asm volatile("cp.async.wait_group 1;\n" ::: "memory");
        __syncthreads();

        const float4* b = reinterpret_cast<const float4*>(&buf[p][0]);

        // ---- pass 1: row max (warp shfl + one shared atomicMax) ----
        float m = -3.402823466e38f;
#pragma unroll
        for (int k = 0; k < 4; k++) {
            float4 v = b[tid + k * THREADS];
            m = fmaxf(m, fmaxf(fmaxf(v.x, v.y), fmaxf(v.z, v.w)));
        }
#pragma unroll
        for (int o = 16; o > 0; o >>= 1)
            m = fmaxf(m, __shfl_xor_sync(0xffffffffu, m, o));
        if (lane == 0) atomicMax(&sh_maxbits, enc_f(m));
        __syncthreads();

        const float thresh = dec_f(sh_maxbits) - 1.0f;   // tau* >= thresh always

        // ---- pass 2: gather candidates (x > rowmax - 1) ----
#pragma unroll
        for (int k = 0; k < 4; k++) {
            float4 v = b[tid + k * THREADS];
            float vals[4] = {v.x, v.y, v.z, v.w};
#pragma unroll
            for (int j = 0; j < 4; j++) {
                if (vals[j] > thresh) {
                    int q = atomicAdd(&sh_cnt, 1);
                    if (q < CAND_CAP) cand[q] = vals[j];
                }
            }
        }
        __syncthreads();

        // ---- warp 0: Michelot fixed point (exact); full-row fallback ----
        if (wid == 0) {
            int n = sh_cnt;
            const float* src = cand;
            if (n > CAND_CAP) { n = N_COLS; src = &buf[p][0]; }  // rare, exact
            float t = thresh;
            int c_prev = -1;
            for (;;) {
                float s = 0.0f;
                int   c = 0;
                for (int i = lane; i < n; i += 32) {
                    float z = src[i];
                    if (z > t) { s += z; c++; }
                }
#pragma unroll
                for (int o = 16; o > 0; o >>= 1) {
                    s += __shfl_xor_sync(0xffffffffu, s, o);
                    c += __shfl_xor_sync(0xffffffffu, c, o);
                }
                if (c == c_prev) break;        // support stabilized -> exact tau
                t = (s - 1.0f) / (float)c;     // c >= 1 (rowmax in support)
                c_prev = c;
            }
            if (lane == 0) sh_tau = t;
        }
        __syncthreads();
        const float tau = sh_tau;

        // ---- pass 3: write max(x - tau, 0), streaming stores ----
        float4* orow = reinterpret_cast<float4*>(out + (size_t)r * N_COLS);
#pragma unroll
        for (int k = 0; k < 4; k++) {
            float4 v = b[tid + k * THREADS];
            float4 o;
            o.x = fmaxf(v.x - tau, 0.0f);
            o.y = fmaxf(v.y - tau, 0.0f);
            o.z = fmaxf(v.z - tau, 0.0f);
            o.w = fmaxf(v.w - tau, 0.0f);
            __stcs(&orow[tid + k * THREADS], o);
        }
    }
}

extern "C" void kernel_launch(void* const* d_in, const int* in_sizes, int n_in,
                              void* d_out, int out_size) {
    const float* x = (const float*)d_in[0];
    float* out = (float*)d_out;
    const int rows = in_sizes[0] / N_COLS;   // 16384
    sparsemax_kernel<<<NBLOCKS, THREADS>>>(x, out, rows);
}